// round 8
// baseline (speedup 1.0000x reference)
#include <cuda_runtime.h>
#include <cstdint>

// Neighborlist brute N^2, upper-triangular pairs, PBC minimum image.
// N=6000 -> P = 17,997,000 pairs (divisible by 4).
// Output buffer: float32, concatenation of the reference tuple:
//   [0,    P)   : masked i indices (-1 if out of cutoff)
//   [P,   2P)   : masked j indices
//   [2P,  3P)   : d_ij (0 if out of cutoff)
//   [3P,  6P)   : r_ij row-major [P,3] (0 if out of cutoff)
//
// Round 8: float4-repacked positions (one LDG.128 per j), all-int32 index
// math, single-row fast path. 4 pairs/thread, 6x STG.128 per thread.

#define N_PART   6000
#define P_TOTAL  17997000      // N*(N-1)/2, fits int32
#define CUTOFF_F 0.5f
#define N_THREADS_TOTAL (P_TOTAL / 4)   // 4,499,250

// Padded positions: xyz + pad. 6000 * 16B = 96 KB, L2/L1 resident.
__device__ float4 g_pos4[N_PART];

__global__ void repack_kernel(const float* __restrict__ pos) {
    int n = blockIdx.x * blockDim.x + threadIdx.x;
    if (n < N_PART) {
        g_pos4[n] = make_float4(pos[3 * n + 0], pos[3 * n + 1], pos[3 * n + 2], 0.0f);
    }
}

__device__ __forceinline__ int row_off(int i) {
    // offset of first pair of row i in triu(k=1) ordering (fits int32)
    return i * (2 * N_PART - i - 1) / 2;
}

// Bitwise-identical to: m = fmodf(r + halfL, L); if (m != 0 && m < 0) m += L;
// return m - halfL;  -- valid since positions in [0, L) => t = r+halfL in (-L/2, 3L/2):
//   t >= L : fmod = t - L (Sterbenz-exact true remainder)
//   0<=t<L : fmod = t
//   t <  0 : fmod = t exactly, then +L rounds identically to the reference path
__device__ __forceinline__ float floormod_wrap(float r, float L, float halfL) {
    float t = __fadd_rn(r, halfL);
    float m = t;
    m = (t >= L)   ? __fadd_rn(t, -L) : m;
    m = (t < 0.0f) ? __fadd_rn(t,  L) : m;
    return __fadd_rn(m, -halfL);
}

struct PairOut { float fi, fj, fd, rx, ry, rz; };

__device__ __forceinline__ void compute_pair(
    const float4 pi, const float4 pj, int i, int j,
    int periodic, float Lx, float Ly, float Lz, float hx, float hy, float hz,
    PairOut& o)
{
    float rx = __fadd_rn(pi.x, -pj.x);
    float ry = __fadd_rn(pi.y, -pj.y);
    float rz = __fadd_rn(pi.z, -pj.z);

    if (periodic) {
        rx = floormod_wrap(rx, Lx, hx);
        ry = floormod_wrap(ry, Ly, hy);
        rz = floormod_wrap(rz, Lz, hz);
    }

    // XLA order: rounded squares, then ((x2 + y2) + z2). No FMA contraction.
    float x2 = __fmul_rn(rx, rx);
    float y2 = __fmul_rn(ry, ry);
    float z2 = __fmul_rn(rz, rz);
    float d2 = __fadd_rn(__fadd_rn(x2, y2), z2);
    float d  = __fsqrt_rn(d2);
    bool in_cut = (d <= CUTOFF_F);

    o.fi = in_cut ? (float)i : -1.0f;
    o.fj = in_cut ? (float)j : -1.0f;
    o.fd = in_cut ? d : 0.0f;
    o.rx = in_cut ? rx : 0.0f;
    o.ry = in_cut ? ry : 0.0f;
    o.rz = in_cut ? rz : 0.0f;
}

__global__ __launch_bounds__(256)
void neighborlist_kernel(const float* __restrict__ box,
                         const int* __restrict__ is_periodic,
                         float* __restrict__ out)
{
    int t = blockIdx.x * blockDim.x + threadIdx.x;
    if (t >= N_THREADS_TOTAL) return;
    int p0 = t * 4;

    // ---- invert p0 -> (i, j): f32 estimate + bounded int32 fixup ----
    // off(i) = i*(2N-1-i)/2 <= p  =>  i ~ ((2N-1) - sqrt((2N-1)^2 - 8p)) / 2
    const float twoNm1 = 2.0f * N_PART - 1.0f;
    int disc_i = (2 * N_PART - 1) * (2 * N_PART - 1) - 8 * p0;   // exact int32
    float s = __fsqrt_rn(__int2float_rn(disc_i));
    int i = (int)((twoNm1 - s) * 0.5f);
    if (i > N_PART - 2) i = N_PART - 2;
    if (i < 0) i = 0;
    while (i < N_PART - 2 && row_off(i + 1) <= p0) ++i;   // bounded fixup
    while (i > 0 && row_off(i) > p0) --i;
    int j = i + 1 + (p0 - row_off(i));

    const int periodic = __ldg(is_periodic);
    const float Lx = __ldg(&box[0]);
    const float Ly = __ldg(&box[4]);
    const float Lz = __ldg(&box[8]);
    const float hx = __fmul_rn(Lx, 0.5f);
    const float hy = __fmul_rn(Ly, 0.5f);
    const float hz = __fmul_rn(Lz, 0.5f);

    PairOut o[4];

    if (j + 3 <= N_PART - 1) {
        // ---- fast path (~99.9%): all 4 pairs in row i ----
        float4 pi = __ldg(&g_pos4[i]);
        #pragma unroll
        for (int k = 0; k < 4; ++k) {
            float4 pj = __ldg(&g_pos4[j + k]);
            compute_pair(pi, pj, i, j + k, periodic, Lx, Ly, Lz, hx, hy, hz, o[k]);
        }
    } else {
        // ---- slow path: crosses row boundary ----
        int ii = i, jj = j;
        #pragma unroll
        for (int k = 0; k < 4; ++k) {
            float4 pi = __ldg(&g_pos4[ii]);
            float4 pj = __ldg(&g_pos4[jj]);
            compute_pair(pi, pj, ii, jj, periodic, Lx, Ly, Lz, hx, hy, hz, o[k]);
            ++jj;
            if (jj >= N_PART) { ++ii; jj = ii + 1; }
        }
    }

    // ---- vectorized stores: p0 % 4 == 0 and all region bases % 4 == 0 ----
    float4* oi  = (float4*)(out + p0);
    float4* oj  = (float4*)(out + P_TOTAL + p0);
    float4* od  = (float4*)(out + 2 * P_TOTAL + p0);
    float4* orr = (float4*)(out + 3 * P_TOTAL + 3 * p0);

    *oi = make_float4(o[0].fi, o[1].fi, o[2].fi, o[3].fi);
    *oj = make_float4(o[0].fj, o[1].fj, o[2].fj, o[3].fj);
    *od = make_float4(o[0].fd, o[1].fd, o[2].fd, o[3].fd);
    orr[0] = make_float4(o[0].rx, o[0].ry, o[0].rz, o[1].rx);
    orr[1] = make_float4(o[1].ry, o[1].rz, o[2].rx, o[2].ry);
    orr[2] = make_float4(o[2].rz, o[3].rx, o[3].ry, o[3].rz);
}

extern "C" void kernel_launch(void* const* d_in, const int* in_sizes, int n_in,
                              void* d_out, int out_size)
{
    const float* pos = (const float*)d_in[0];       // [6000, 3] float32
    const float* box = (const float*)d_in[1];       // [3, 3] float32
    const int*   per = (const int*)d_in[2];         // scalar int32

    float* out = (float*)d_out;

    repack_kernel<<<(N_PART + 255) / 256, 256>>>(pos);

    const int threads = 256;
    const int blocks = (N_THREADS_TOTAL + threads - 1) / threads;  // 17,576
    neighborlist_kernel<<<blocks, threads>>>(box, per, out);
}

// round 9
// speedup vs baseline: 1.3520x; 1.3520x over previous
#include <cuda_runtime.h>
#include <cstdint>

// Neighborlist brute N^2, upper-triangular pairs, PBC minimum image.
// N=6000 -> P = 17,997,000 pairs. Output float32, concatenated tuple:
//   [0,    P)   : masked i indices (-1 if out of cutoff)
//   [P,   2P)   : masked j indices
//   [2P,  3P)   : d_ij (0 if out of cutoff)
//   [3P,  6P)   : r_ij row-major [P,3] (0 if out of cutoff)
//
// Round 9: warp-coalesced mapping. Warp w owns pairs [128w, 128w+128);
// thread `lane` handles pairs 128w + 32u + lane (u=0..3). All loads and the
// i/j/d stores are warp-coalesced; index inversion is warp-uniform (fast path).

#define N_PART   6000
#define P_TOTAL  17997000      // N*(N-1)/2, fits int32
#define CUTOFF_F 0.5f
#define WARPS_TOTAL ((P_TOTAL + 127) / 128)   // 140,602

__device__ __forceinline__ int row_off(int i) {
    // offset of first pair of row i in triu(k=1) ordering (fits int32)
    return i * (2 * N_PART - i - 1) / 2;
}

// Bitwise-identical to: m = fmodf(r + halfL, L); if (m != 0 && m < 0) m += L;
// return m - halfL;  -- valid since positions in [0, L) => t = r+halfL in (-L/2, 3L/2):
//   t >= L : fmod = t - L (Sterbenz-exact true remainder)
//   0<=t<L : fmod = t
//   t <  0 : fmod = t exactly, then +L rounds identically to the reference path
__device__ __forceinline__ float floormod_wrap(float r, float L, float halfL) {
    float t = __fadd_rn(r, halfL);
    float m = t;
    m = (t >= L)   ? __fadd_rn(t, -L) : m;
    m = (t < 0.0f) ? __fadd_rn(t,  L) : m;
    return __fadd_rn(m, -halfL);
}

// invert pair index p -> i (row), via f32 sqrt estimate + bounded fixup
__device__ __forceinline__ int invert_row(int p) {
    const float twoNm1 = 2.0f * N_PART - 1.0f;
    int disc_i = (2 * N_PART - 1) * (2 * N_PART - 1) - 8 * p;   // exact int32
    float s = __fsqrt_rn(__int2float_rn(disc_i));
    int i = (int)((twoNm1 - s) * 0.5f);
    if (i > N_PART - 2) i = N_PART - 2;
    if (i < 0) i = 0;
    while (i < N_PART - 2 && row_off(i + 1) <= p) ++i;
    while (i > 0 && row_off(i) > p) --i;
    return i;
}

__device__ __forceinline__ void compute_store(
    const float* __restrict__ pos, float* __restrict__ out,
    int i, int j, int p,
    float xi, float yi, float zi,
    int periodic, float Lx, float Ly, float Lz, float hx, float hy, float hz)
{
    float xj = __ldg(&pos[3 * j + 0]);
    float yj = __ldg(&pos[3 * j + 1]);
    float zj = __ldg(&pos[3 * j + 2]);

    float rx = __fadd_rn(xi, -xj);
    float ry = __fadd_rn(yi, -yj);
    float rz = __fadd_rn(zi, -zj);

    if (periodic) {
        rx = floormod_wrap(rx, Lx, hx);
        ry = floormod_wrap(ry, Ly, hy);
        rz = floormod_wrap(rz, Lz, hz);
    }

    // XLA order: rounded squares, then ((x2 + y2) + z2). No FMA contraction.
    float x2 = __fmul_rn(rx, rx);
    float y2 = __fmul_rn(ry, ry);
    float z2 = __fmul_rn(rz, rz);
    float d2 = __fadd_rn(__fadd_rn(x2, y2), z2);
    float d  = __fsqrt_rn(d2);
    bool in_cut = (d <= CUTOFF_F);

    out[p]              = in_cut ? (float)i : -1.0f;   // oi
    out[P_TOTAL + p]    = in_cut ? (float)j : -1.0f;   // oj
    out[2 * P_TOTAL + p] = in_cut ? d : 0.0f;          // od
    int rbase = 3 * P_TOTAL + 3 * p;
    out[rbase + 0] = in_cut ? rx : 0.0f;
    out[rbase + 1] = in_cut ? ry : 0.0f;
    out[rbase + 2] = in_cut ? rz : 0.0f;
}

__global__ __launch_bounds__(256)
void neighborlist_kernel(const float* __restrict__ pos,
                         const float* __restrict__ box,
                         const int* __restrict__ is_periodic,
                         float* __restrict__ out)
{
    int warp_g = (blockIdx.x * blockDim.x + threadIdx.x) >> 5;
    int lane   = threadIdx.x & 31;
    if (warp_g >= WARPS_TOTAL) return;
    int base = warp_g * 128;        // first pair of this warp (fits int32)

    const int periodic = __ldg(is_periodic);
    const float Lx = __ldg(&box[0]);
    const float Ly = __ldg(&box[4]);
    const float Lz = __ldg(&box[8]);
    const float hx = __fmul_rn(Lx, 0.5f);
    const float hy = __fmul_rn(Ly, 0.5f);
    const float hz = __fmul_rn(Lz, 0.5f);

    // warp-uniform inversion of the warp's first pair
    int i0 = invert_row(base);
    int j0 = i0 + 1 + (base - row_off(i0));

    if (j0 + 127 <= N_PART - 1 && base + 127 < P_TOTAL) {
        // ---- fast path (~96% of warps): all 128 pairs in row i0 ----
        float xi = __ldg(&pos[3 * i0 + 0]);   // warp-uniform loads (1 wf each)
        float yi = __ldg(&pos[3 * i0 + 1]);
        float zi = __ldg(&pos[3 * i0 + 2]);
        #pragma unroll
        for (int u = 0; u < 4; ++u) {
            int q = u * 32 + lane;
            compute_store(pos, out, i0, j0 + q, base + q,
                          xi, yi, zi, periodic, Lx, Ly, Lz, hx, hy, hz);
        }
    } else {
        // ---- slow path: row boundary inside warp, or tail ----
        #pragma unroll
        for (int u = 0; u < 4; ++u) {
            int p = base + u * 32 + lane;
            if (p >= P_TOTAL) continue;
            int i = invert_row(p);
            int j = i + 1 + (p - row_off(i));
            float xi = __ldg(&pos[3 * i + 0]);
            float yi = __ldg(&pos[3 * i + 1]);
            float zi = __ldg(&pos[3 * i + 2]);
            compute_store(pos, out, i, j, p,
                          xi, yi, zi, periodic, Lx, Ly, Lz, hx, hy, hz);
        }
    }
}

extern "C" void kernel_launch(void* const* d_in, const int* in_sizes, int n_in,
                              void* d_out, int out_size)
{
    const float* pos = (const float*)d_in[0];       // [6000, 3] float32
    const float* box = (const float*)d_in[1];       // [3, 3] float32
    const int*   per = (const int*)d_in[2];         // scalar int32

    float* out = (float*)d_out;

    const int threads = 256;
    const long long total_threads = (long long)WARPS_TOTAL * 32;   // 4,499,264
    const int blocks = (int)((total_threads + threads - 1) / threads);  // 17,576
    neighborlist_kernel<<<blocks, threads>>>(pos, box, per, out);
}